// round 2
// baseline (speedup 1.0000x reference)
#include <cuda_runtime.h>
#include <cuda_bf16.h>
#include <math_constants.h>

#define BB      2
#define FF      8192
#define QQ      4096
#define NPTS    (BB * QQ)        // 8192
#define NSPLIT  8
#define FSEG    (FF / NSPLIT)    // 1024
#define TILE    256
#define BLK     128

// Scratch for split-K reduction (no allocations allowed)
__device__ float g_best_d2[NSPLIT * NPTS];
__device__ int   g_best_idx[NSPLIT * NPTS];

// Reference: n / where(d==0, 1, d)  -- full-precision division to match XLA
__device__ __forceinline__ float safe_div(float n, float d) {
    return n / ((d == 0.0f) ? 1.0f : d);
}

// Ericson closest-point barycentrics, matching the jnp.select priority order
// (cond1 highest priority -> apply overwrites in reverse order).
// Returns (u, v, w); u == 1 - v - w in every branch of the reference.
__device__ __forceinline__ void bary_uvw(
    float ax, float ay, float az,
    float bx, float by, float bz,
    float cx, float cy, float cz,
    float px, float py, float pz,
    float& u, float& v, float& w)
{
    float abx = bx - ax, aby = by - ay, abz = bz - az;
    float acx = cx - ax, acy = cy - ay, acz = cz - az;
    float apx = px - ax, apy = py - ay, apz = pz - az;
    float d1 = abx * apx + aby * apy + abz * apz;
    float d2 = acx * apx + acy * apy + acz * apz;
    float bpx = px - bx, bpy = py - by, bpz = pz - bz;
    float d3 = abx * bpx + aby * bpy + abz * bpz;
    float d4 = acx * bpx + acy * bpy + acz * bpz;
    float cpx = px - cx, cpy = py - cy, cpz = pz - cz;
    float d5 = abx * cpx + aby * cpy + abz * cpz;
    float d6 = acx * cpx + acy * cpy + acz * cpz;
    float vc = d1 * d4 - d3 * d2;
    float vb = d5 * d2 - d1 * d6;
    float va = d3 * d6 - d5 * d4;

    // default: interior
    float inv = safe_div(1.0f, va + vb + vc);
    v = vb * inv;
    w = vc * inv;

    // cond6: edge BC
    if (va <= 0.0f && d4 >= d3 && d5 >= d6) {
        float num = d4 - d3;
        float wbc = safe_div(num, num + (d5 - d6));
        v = 1.0f - wbc; w = wbc;
    }
    // cond5: edge AC
    if (vb <= 0.0f && d2 >= 0.0f && d6 <= 0.0f) {
        v = 0.0f; w = safe_div(d2, d2 - d6);
    }
    // cond4: vertex C
    if (d6 >= 0.0f && d5 <= d6) { v = 0.0f; w = 1.0f; }
    // cond3: edge AB
    if (vc <= 0.0f && d1 >= 0.0f && d3 <= 0.0f) {
        v = safe_div(d1, d1 - d3); w = 0.0f;
    }
    // cond2: vertex B
    if (d3 >= 0.0f && d4 <= d3) { v = 1.0f; w = 0.0f; }
    // cond1: vertex A
    if (d1 <= 0.0f && d2 <= 0.0f) { v = 0.0f; w = 0.0f; }

    u = 1.0f - v - w;
}

// Kernel 1: brute-force closest-triangle search over one F-segment per block-row.
// grid = (NPTS/BLK, NSPLIT), block = BLK. Triangles staged in smem tiles.
__global__ void __launch_bounds__(BLK)
p2m_search_kernel(const float* __restrict__ tri, const float* __restrict__ pts)
{
    __shared__ float s_tri[TILE * 9];

    const int pid = blockIdx.x * BLK + threadIdx.x;   // global point id
    const int b   = pid >> 12;                         // batch (Q = 4096)
    const float* tb = tri + (size_t)b * FF * 9;

    const float px = pts[pid * 3 + 0];
    const float py = pts[pid * 3 + 1];
    const float pz = pts[pid * 3 + 2];

    const int f0 = blockIdx.y * FSEG;

    float best = CUDART_INF_F;
    int   bidx = f0;

    for (int t0 = 0; t0 < FSEG; t0 += TILE) {
        __syncthreads();
        const float* src = tb + (size_t)(f0 + t0) * 9;
        #pragma unroll
        for (int i = threadIdx.x; i < TILE * 9; i += BLK)
            s_tri[i] = src[i];
        __syncthreads();

        for (int j = 0; j < TILE; ++j) {
            const float* t = s_tri + j * 9;
            float ax = t[0], ay = t[1], az = t[2];
            float bx = t[3], by = t[4], bz = t[5];
            float cx = t[6], cy = t[7], cz = t[8];

            float u, v, w;
            bary_uvw(ax, ay, az, bx, by, bz, cx, cy, cz, px, py, pz, u, v, w);

            // cp = u*a + v*b + w*c (reference einsum association), d2 = |cp - p|^2
            float qx = u * ax + v * bx + w * cx;
            float qy = u * ay + v * by + w * cy;
            float qz = u * az + v * bz + w * cz;
            float dx = qx - px, dy = qy - py, dz = qz - pz;
            float dist = dx * dx + dy * dy + dz * dz;

            if (dist < best) {           // strict < : first-occurrence argmin
                best = dist;
                bidx = f0 + t0 + j;
            }
        }
    }

    g_best_d2 [blockIdx.y * NPTS + pid] = best;
    g_best_idx[blockIdx.y * NPTS + pid] = bidx;
}

// Kernel 2: reduce splits (ascending order keeps first-min), recompute bary on
// the winning triangle, clamp, gather normals/cmaps/faces, write all outputs.
// Output layout (float32): residual[8192*3] | normals[8192*3] | cmaps[8192*3] | idx[8192]
__global__ void p2m_finalize_kernel(
    const float* __restrict__ tri, const float* __restrict__ pts,
    const float* __restrict__ nrm, const float* __restrict__ cmp,
    const int*   __restrict__ faces, float* __restrict__ out)
{
    const int pid = blockIdx.x * blockDim.x + threadIdx.x;
    if (pid >= NPTS) return;

    float best = CUDART_INF_F;
    int   bidx = 0;
    #pragma unroll
    for (int s = 0; s < NSPLIT; ++s) {
        float d = g_best_d2[s * NPTS + pid];
        if (d < best) { best = d; bidx = g_best_idx[s * NPTS + pid]; }
    }

    const int b = pid >> 12;
    const size_t fbase = (size_t)(b * FF + bidx);

    const float px = pts[pid * 3 + 0];
    const float py = pts[pid * 3 + 1];
    const float pz = pts[pid * 3 + 2];

    const float* t = tri + fbase * 9;
    float ax = t[0], ay = t[1], az = t[2];
    float bx = t[3], by = t[4], bz = t[5];
    float cx = t[6], cy = t[7], cz = t[8];

    float u, v, w;
    bary_uvw(ax, ay, az, bx, by, bz, cx, cy, cz, px, py, pz, u, v, w);

    // clip to [0, 1]
    u = fminf(fmaxf(u, 0.0f), 1.0f);
    v = fminf(fmaxf(v, 0.0f), 1.0f);
    w = fminf(fmaxf(w, 0.0f), 1.0f);

    // residual = (u*a + v*b + w*c) - p
    out[pid * 3 + 0] = (u * ax + v * bx + w * cx) - px;
    out[pid * 3 + 1] = (u * ay + v * by + w * cy) - py;
    out[pid * 3 + 2] = (u * az + v * bz + w * cz) - pz;

    const float* n = nrm + fbase * 9;
    out[NPTS * 3 + pid * 3 + 0] = u * n[0] + v * n[3] + w * n[6];
    out[NPTS * 3 + pid * 3 + 1] = u * n[1] + v * n[4] + w * n[7];
    out[NPTS * 3 + pid * 3 + 2] = u * n[2] + v * n[5] + w * n[8];

    const float* cm = cmp + fbase * 9;
    out[NPTS * 6 + pid * 3 + 0] = u * cm[0] + v * cm[3] + w * cm[6];
    out[NPTS * 6 + pid * 3 + 1] = u * cm[1] + v * cm[4] + w * cm[7];
    out[NPTS * 6 + pid * 3 + 2] = u * cm[2] + v * cm[5] + w * cm[8];

    // argmax of clipped bcs, first occurrence
    int k = (u >= v && u >= w) ? 0 : ((v >= w) ? 1 : 2);
    out[NPTS * 9 + pid] = (float)faces[fbase * 3 + k];
}

extern "C" void kernel_launch(void* const* d_in, const int* in_sizes, int n_in,
                              void* d_out, int out_size)
{
    const float* tri   = (const float*)d_in[0];   // [B,F,3,3]
    const float* pts   = (const float*)d_in[1];   // [B,Q,3]
    const float* nrm   = (const float*)d_in[2];   // [B,F,3,3]
    const float* cmp   = (const float*)d_in[3];   // [B,F,3,3]
    const int*   faces = (const int*)  d_in[4];   // [B,F,3]
    float* out = (float*)d_out;

    dim3 grid1(NPTS / BLK, NSPLIT);
    p2m_search_kernel<<<grid1, BLK>>>(tri, pts);
    p2m_finalize_kernel<<<NPTS / 256, 256>>>(tri, pts, nrm, cmp, faces, out);
}

// round 5
// speedup vs baseline: 2.3102x; 2.3102x over previous
#include <cuda_runtime.h>
#include <cuda_bf16.h>
#include <math_constants.h>

#define BB      2
#define FF      8192
#define QQ      4096
#define NPTS    (BB * QQ)        // 8192
#define NSPLIT  32
#define FSEG    (FF / NSPLIT)    // 256
#define TILE    128
#define BLK     128
#define PPT     2                // points per thread

// Scratch for split-K reduction (no allocations allowed)
__device__ float g_best_d2[NSPLIT * NPTS];
__device__ int   g_best_idx[NSPLIT * NPTS];

// ---------------------------------------------------------------------------
// Exact reference arithmetic (used ONLY in finalize, where outputs are made).
// Matches jnp.select priority via reverse-order overwrites; full div.rn.
// ---------------------------------------------------------------------------
__device__ __forceinline__ float safe_div(float n, float d) {
    return n / ((d == 0.0f) ? 1.0f : d);
}

__device__ __forceinline__ void bary_uvw_exact(
    float ax, float ay, float az,
    float bx, float by, float bz,
    float cx, float cy, float cz,
    float px, float py, float pz,
    float& u, float& v, float& w)
{
    float abx = bx - ax, aby = by - ay, abz = bz - az;
    float acx = cx - ax, acy = cy - ay, acz = cz - az;
    float apx = px - ax, apy = py - ay, apz = pz - az;
    float d1 = abx * apx + aby * apy + abz * apz;
    float d2 = acx * apx + acy * apy + acz * apz;
    float bpx = px - bx, bpy = py - by, bpz = pz - bz;
    float d3 = abx * bpx + aby * bpy + abz * bpz;
    float d4 = acx * bpx + acy * bpy + acz * bpz;
    float cpx = px - cx, cpy = py - cy, cpz = pz - cz;
    float d5 = abx * cpx + aby * cpy + abz * cpz;
    float d6 = acx * cpx + acy * cpy + acz * cpz;
    float vc = d1 * d4 - d3 * d2;
    float vb = d5 * d2 - d1 * d6;
    float va = d3 * d6 - d5 * d4;

    float inv = safe_div(1.0f, va + vb + vc);
    v = vb * inv;
    w = vc * inv;

    if (va <= 0.0f && d4 >= d3 && d5 >= d6) {
        float num = d4 - d3;
        float wbc = safe_div(num, num + (d5 - d6));
        v = 1.0f - wbc; w = wbc;
    }
    if (vb <= 0.0f && d2 >= 0.0f && d6 <= 0.0f) {
        v = 0.0f; w = safe_div(d2, d2 - d6);
    }
    if (d6 >= 0.0f && d5 <= d6) { v = 0.0f; w = 1.0f; }
    if (vc <= 0.0f && d1 >= 0.0f && d3 <= 0.0f) {
        v = safe_div(d1, d1 - d3); w = 0.0f;
    }
    if (d3 >= 0.0f && d4 <= d3) { v = 1.0f; w = 0.0f; }
    if (d1 <= 0.0f && d2 <= 0.0f) { v = 0.0f; w = 0.0f; }

    u = 1.0f - v - w;
}

// ---------------------------------------------------------------------------
// Fast branch-free point-triangle squared distance for the argmin search.
// Triangle packed as:
//   T0 = (ax, ay, az, ab.ab)
//   T1 = (abx, aby, abz, ac.ac)
//   T2 = (acx, acy, acz, ab.ac)
// Single rcp.approx + 1 Newton step (~1-2 ulp). Distances are only compared;
// outputs are recomputed exactly in finalize.
// ---------------------------------------------------------------------------
__device__ __forceinline__ void tri_test(
    const float4 T0, const float4 T1, const float4 T2,
    float px, float py, float pz,
    int fid, float& best, int& bidx)
{
    const float abx = T1.x, aby = T1.y, abz = T1.z;
    const float acx = T2.x, acy = T2.y, acz = T2.z;
    const float abab = T0.w, acac = T1.w, abac = T2.w;

    float apx = px - T0.x, apy = py - T0.y, apz = pz - T0.z;
    float d1 = fmaf(abx, apx, fmaf(aby, apy, abz * apz));
    float d2 = fmaf(acx, apx, fmaf(acy, apy, acz * apz));
    float d3 = d1 - abab;
    float d4 = d2 - abac;
    float d5 = d1 - abac;
    float d6 = d2 - acac;
    float vc = fmaf(d1, d4, -d3 * d2);
    float vb = fmaf(d5, d2, -d1 * d6);
    float va = fmaf(d3, d6, -d5 * d4);

    // default: interior
    float num_v = vb, num_w = vc, den = (va + vb) + vc;

    // reverse-priority overwrites (cond1 wins)
    float nbc = d4 - d3;
    float dbc = nbc + (d5 - d6);
    bool c6 = (va <= 0.0f) & (d4 >= d3) & (d5 >= d6);
    num_v = c6 ? (dbc - nbc) : num_v;  num_w = c6 ? nbc : num_w;  den = c6 ? dbc : den;

    bool c5 = (vb <= 0.0f) & (d2 >= 0.0f) & (d6 <= 0.0f);
    float dac = d2 - d6;
    num_v = c5 ? 0.0f : num_v;  num_w = c5 ? d2 : num_w;  den = c5 ? dac : den;

    bool c4 = (d6 >= 0.0f) & (d5 <= d6);
    num_v = c4 ? 0.0f : num_v;  num_w = c4 ? 1.0f : num_w;  den = c4 ? 1.0f : den;

    bool c3 = (vc <= 0.0f) & (d1 >= 0.0f) & (d3 <= 0.0f);
    float dab = d1 - d3;
    num_v = c3 ? d1 : num_v;  num_w = c3 ? 0.0f : num_w;  den = c3 ? dab : den;

    bool c2 = (d3 >= 0.0f) & (d4 <= d3);
    num_v = c2 ? 1.0f : num_v;  num_w = c2 ? 0.0f : num_w;  den = c2 ? 1.0f : den;

    bool c1 = (d1 <= 0.0f) & (d2 <= 0.0f);
    num_v = c1 ? 0.0f : num_v;  num_w = c1 ? 0.0f : num_w;  den = c1 ? 1.0f : den;

    den = (den == 0.0f) ? 1.0f : den;
    float r;
    asm("rcp.approx.f32 %0, %1;" : "=f"(r) : "f"(den));
    // one Newton step: r' = r + r*(1 - den*r)
    float e = fmaf(-den, r, 1.0f);
    r = fmaf(r, e, r);

    float v = num_v * r, w = num_w * r;

    // q - p = -ap + v*ab + w*ac  (q = a + v*ab + w*ac)
    float dx = fmaf(v, abx, fmaf(w, acx, -apx));
    float dy = fmaf(v, aby, fmaf(w, acy, -apy));
    float dz = fmaf(v, abz, fmaf(w, acz, -apz));
    float dist = fmaf(dx, dx, fmaf(dy, dy, dz * dz));

    if (dist < best) { best = dist; bidx = fid; }   // strict <: first-occurrence
}

// ---------------------------------------------------------------------------
// Kernel 1: brute-force argmin search. 2 points/thread, 32 F-splits.
// grid = (NPTS/(BLK*PPT), NSPLIT), block = BLK.
// ---------------------------------------------------------------------------
__global__ void __launch_bounds__(BLK)
p2m_search_kernel(const float* __restrict__ tri, const float* __restrict__ pts)
{
    __shared__ float4 sT[TILE * 3];

    const int tid = threadIdx.x;
    const int p0  = blockIdx.x * (BLK * PPT) + tid;   // point 0
    const int p1  = p0 + BLK;                          // point 1 (same batch: 256-aligned group)
    const int b   = p0 >> 12;                          // Q = 4096
    const float* tb = tri + (size_t)b * FF * 9;

    const float p0x = pts[p0 * 3 + 0], p0y = pts[p0 * 3 + 1], p0z = pts[p0 * 3 + 2];
    const float p1x = pts[p1 * 3 + 0], p1y = pts[p1 * 3 + 1], p1z = pts[p1 * 3 + 2];

    const int f0 = blockIdx.y * FSEG;

    float best0 = CUDART_INF_F, best1 = CUDART_INF_F;
    int   bidx0 = f0,           bidx1 = f0;

    for (int t0 = 0; t0 < FSEG; t0 += TILE) {
        __syncthreads();
        {
            // one triangle per thread: load 9 floats, precompute invariants
            const float* s = tb + (size_t)(f0 + t0 + tid) * 9;
            float ax = s[0], ay = s[1], az = s[2];
            float bx = s[3], by = s[4], bz = s[5];
            float cx = s[6], cy = s[7], cz = s[8];
            float abx = bx - ax, aby = by - ay, abz = bz - az;
            float acx = cx - ax, acy = cy - ay, acz = cz - az;
            float abab = fmaf(abx, abx, fmaf(aby, aby, abz * abz));
            float acac = fmaf(acx, acx, fmaf(acy, acy, acz * acz));
            float abac = fmaf(abx, acx, fmaf(aby, acy, abz * acz));
            sT[tid * 3 + 0] = make_float4(ax, ay, az, abab);
            sT[tid * 3 + 1] = make_float4(abx, aby, abz, acac);
            sT[tid * 3 + 2] = make_float4(acx, acy, acz, abac);
        }
        __syncthreads();

        #pragma unroll 4
        for (int j = 0; j < TILE; ++j) {
            const float4 T0 = sT[j * 3 + 0];
            const float4 T1 = sT[j * 3 + 1];
            const float4 T2 = sT[j * 3 + 2];
            const int fid = f0 + t0 + j;
            tri_test(T0, T1, T2, p0x, p0y, p0z, fid, best0, bidx0);
            tri_test(T0, T1, T2, p1x, p1y, p1z, fid, best1, bidx1);
        }
    }

    g_best_d2 [blockIdx.y * NPTS + p0] = best0;
    g_best_idx[blockIdx.y * NPTS + p0] = bidx0;
    g_best_d2 [blockIdx.y * NPTS + p1] = best1;
    g_best_idx[blockIdx.y * NPTS + p1] = bidx1;
}

// ---------------------------------------------------------------------------
// Kernel 2: reduce splits (ascending keeps first-min), recompute exact bary on
// winning triangle, clamp, gather, write outputs.
// Output (float32): residual[8192*3] | normals[8192*3] | cmaps[8192*3] | idx[8192]
// ---------------------------------------------------------------------------
__global__ void p2m_finalize_kernel(
    const float* __restrict__ tri, const float* __restrict__ pts,
    const float* __restrict__ nrm, const float* __restrict__ cmp,
    const int*   __restrict__ faces, float* __restrict__ out)
{
    const int pid = blockIdx.x * blockDim.x + threadIdx.x;
    if (pid >= NPTS) return;

    float best = CUDART_INF_F;
    int   bidx = 0;
    #pragma unroll
    for (int s = 0; s < NSPLIT; ++s) {
        float d = g_best_d2[s * NPTS + pid];
        int   i = g_best_idx[s * NPTS + pid];
        if (d < best) { best = d; bidx = i; }
    }

    const int b = pid >> 12;
    const size_t fbase = (size_t)(b * FF + bidx);

    const float px = pts[pid * 3 + 0];
    const float py = pts[pid * 3 + 1];
    const float pz = pts[pid * 3 + 2];

    const float* t = tri + fbase * 9;
    float ax = t[0], ay = t[1], az = t[2];
    float bx = t[3], by = t[4], bz = t[5];
    float cx = t[6], cy = t[7], cz = t[8];

    float u, v, w;
    bary_uvw_exact(ax, ay, az, bx, by, bz, cx, cy, cz, px, py, pz, u, v, w);

    u = fminf(fmaxf(u, 0.0f), 1.0f);
    v = fminf(fmaxf(v, 0.0f), 1.0f);
    w = fminf(fmaxf(w, 0.0f), 1.0f);

    out[pid * 3 + 0] = (u * ax + v * bx + w * cx) - px;
    out[pid * 3 + 1] = (u * ay + v * by + w * cy) - py;
    out[pid * 3 + 2] = (u * az + v * bz + w * cz) - pz;

    const float* n = nrm + fbase * 9;
    out[NPTS * 3 + pid * 3 + 0] = u * n[0] + v * n[3] + w * n[6];
    out[NPTS * 3 + pid * 3 + 1] = u * n[1] + v * n[4] + w * n[7];
    out[NPTS * 3 + pid * 3 + 2] = u * n[2] + v * n[5] + w * n[8];

    const float* cm = cmp + fbase * 9;
    out[NPTS * 6 + pid * 3 + 0] = u * cm[0] + v * cm[3] + w * cm[6];
    out[NPTS * 6 + pid * 3 + 1] = u * cm[1] + v * cm[4] + w * cm[7];
    out[NPTS * 6 + pid * 3 + 2] = u * cm[2] + v * cm[5] + w * cm[8];

    int k = (u >= v && u >= w) ? 0 : ((v >= w) ? 1 : 2);
    out[NPTS * 9 + pid] = (float)faces[fbase * 3 + k];
}

extern "C" void kernel_launch(void* const* d_in, const int* in_sizes, int n_in,
                              void* d_out, int out_size)
{
    const float* tri   = (const float*)d_in[0];   // [B,F,3,3]
    const float* pts   = (const float*)d_in[1];   // [B,Q,3]
    const float* nrm   = (const float*)d_in[2];   // [B,F,3,3]
    const float* cmp   = (const float*)d_in[3];   // [B,F,3,3]
    const int*   faces = (const int*)  d_in[4];   // [B,F,3]
    float* out = (float*)d_out;

    dim3 grid1(NPTS / (BLK * PPT), NSPLIT);       // (32, 32)
    p2m_search_kernel<<<grid1, BLK>>>(tri, pts);
    p2m_finalize_kernel<<<NPTS / 256, 256>>>(tri, pts, nrm, cmp, faces, out);
}

// round 7
// speedup vs baseline: 2.8669x; 1.2409x over previous
#include <cuda_runtime.h>
#include <cuda_bf16.h>
#include <math_constants.h>

#define BB      2
#define FF      8192
#define QQ      4096
#define NPTS    (BB * QQ)        // 8192
#define NSPLIT  32
#define FSEG    (FF / NSPLIT)    // 256
#define TILE    128
#define BLK     128
#define PPT     2                // points per thread (f32x2 lanes)
#define NREC    12               // ulonglong2 per triangle record

typedef unsigned long long u64;

// Per-point argmin key: (float_bits(d2) << 32) | fid. atomicMin over unique
// keys is order-independent; smaller fid wins exact ties = first-occurrence.
__device__ u64 g_key[NPTS];

// ---------------------------------------------------------------------------
// f32x2 packed helpers (sm_103a). Packed u64 = aligned register pair, so
// PK/UPK are register-renaming no-ops (MOV at worst).
// ---------------------------------------------------------------------------
__device__ __forceinline__ u64 PK(float lo, float hi) {
    u64 r; asm("mov.b64 %0, {%1, %2};" : "=l"(r) : "f"(lo), "f"(hi)); return r;
}
__device__ __forceinline__ void UPK(u64 p, float& lo, float& hi) {
    asm("mov.b64 {%0, %1}, %2;" : "=f"(lo), "=f"(hi) : "l"(p));
}
__device__ __forceinline__ u64 FMA2(u64 a, u64 b, u64 c) {
    u64 d; asm("fma.rn.f32x2 %0, %1, %2, %3;" : "=l"(d) : "l"(a), "l"(b), "l"(c)); return d;
}
__device__ __forceinline__ u64 ADD2(u64 a, u64 b) {
    u64 d; asm("add.rn.f32x2 %0, %1, %2;" : "=l"(d) : "l"(a), "l"(b)); return d;
}
__device__ __forceinline__ u64 MUL2(u64 a, u64 b) {
    u64 d; asm("mul.rn.f32x2 %0, %1, %2;" : "=l"(d) : "l"(a), "l"(b)); return d;
}
__device__ __forceinline__ u64 NEG2(u64 a) {   // ALU/LOP pipe sign flip
    u64 d; asm("xor.b64 %0, %1, 0x8000000080000000;" : "=l"(d) : "l"(a)); return d;
}

__device__ __forceinline__ float clamp01(float t) {
    return fminf(fmaxf(t, 0.0f), 1.0f);
}
// clamp both lanes of a packed pair (scalar FMNMX on halves; regs alias)
__device__ __forceinline__ u64 CLAMP01_2(u64 t) {
    float lo, hi; UPK(t, lo, hi);
    return PK(clamp01(lo), clamp01(hi));
}

// ---------------------------------------------------------------------------
// Exact reference arithmetic (finalize only — produces the actual outputs).
// ---------------------------------------------------------------------------
__device__ __forceinline__ float safe_div(float n, float d) {
    return n / ((d == 0.0f) ? 1.0f : d);
}

__device__ __forceinline__ void bary_uvw_exact(
    float ax, float ay, float az,
    float bx, float by, float bz,
    float cx, float cy, float cz,
    float px, float py, float pz,
    float& u, float& v, float& w)
{
    float abx = bx - ax, aby = by - ay, abz = bz - az;
    float acx = cx - ax, acy = cy - ay, acz = cz - az;
    float apx = px - ax, apy = py - ay, apz = pz - az;
    float d1 = abx * apx + aby * apy + abz * apz;
    float d2 = acx * apx + acy * apy + acz * apz;
    float bpx = px - bx, bpy = py - by, bpz = pz - bz;
    float d3 = abx * bpx + aby * bpy + abz * bpz;
    float d4 = acx * bpx + acy * bpy + acz * bpz;
    float cpx = px - cx, cpy = py - cy, cpz = pz - cz;
    float d5 = abx * cpx + aby * cpy + abz * cpz;
    float d6 = acx * cpx + acy * cpy + acz * cpz;
    float vc = d1 * d4 - d3 * d2;
    float vb = d5 * d2 - d1 * d6;
    float va = d3 * d6 - d5 * d4;

    float inv = safe_div(1.0f, va + vb + vc);
    v = vb * inv;
    w = vc * inv;

    if (va <= 0.0f && d4 >= d3 && d5 >= d6) {
        float num = d4 - d3;
        float wbc = safe_div(num, num + (d5 - d6));
        v = 1.0f - wbc; w = wbc;
    }
    if (vb <= 0.0f && d2 >= 0.0f && d6 <= 0.0f) {
        v = 0.0f; w = safe_div(d2, d2 - d6);
    }
    if (d6 >= 0.0f && d5 <= d6) { v = 0.0f; w = 1.0f; }
    if (vc <= 0.0f && d1 >= 0.0f && d3 <= 0.0f) {
        v = safe_div(d1, d1 - d3); w = 0.0f;
    }
    if (d3 >= 0.0f && d4 <= d3) { v = 1.0f; w = 0.0f; }
    if (d1 <= 0.0f && d2 <= 0.0f) { v = 0.0f; w = 0.0f; }

    u = 1.0f - v - w;
}

// ---------------------------------------------------------------------------
// Kernel 0: reset argmin keys (graph-replay safe).
// ---------------------------------------------------------------------------
__global__ void p2m_init_kernel() {
    int i = blockIdx.x * blockDim.x + threadIdx.x;
    if (i < NPTS) g_key[i] = ~0ull;
}

// ---------------------------------------------------------------------------
// Kernel 1: brute-force argmin search, f32x2-packed, 2 points/thread.
//
// Per-triangle smem record: 24 packed-doubled u64 (= 12 ulonglong2, 192 B):
//   [ 0.. 2] -a          [ 3.. 5] -b        [ 6.. 8] ab
//   [ 9..11] ac          [12..14] bc        [15] acac  [16] -abac
//   [17] abab            [18] invdet        [19] invabab
//   [20] invacac         [21] invbcbc       [22] det   [23] pad
//
// Candidates (ALL vector-form -> eps-relative distance error):
//   interior: |v*ab + w*ac - ap|^2   (v=vb*invdet, w=vc*invdet), masked by
//             vb>=0 && vc>=0 && vb+vc<=det
//   edge AB:  |clamp01(d1*invabab)*ab - ap|^2
//   edge AC:  |clamp01(d2*invacac)*ac - ap|^2
//   edge BC:  |clamp01((bc.bp)*invbcbc)*bc - bp|^2
// min of candidates == exact Ericson distance (identities: d1-d3=abab,
// d2-d6=acac, (d4-d3)+(d5-d6)=bcbc, d4-d3=bc.bp, va+vb+vc=det).
// ---------------------------------------------------------------------------
__global__ void __launch_bounds__(BLK)
p2m_search_kernel(const float* __restrict__ tri, const float* __restrict__ pts)
{
    __shared__ ulonglong2 sT[TILE][NREC];

    const int tid = threadIdx.x;
    const int p0  = blockIdx.x * (BLK * PPT) + tid;
    const int p1  = p0 + BLK;               // same 256-group -> same batch
    const int b   = p0 >> 12;               // Q = 4096
    const float* tb = tri + (size_t)b * FF * 9;

    const u64 ppx = PK(pts[p0 * 3 + 0], pts[p1 * 3 + 0]);
    const u64 ppy = PK(pts[p0 * 3 + 1], pts[p1 * 3 + 1]);
    const u64 ppz = PK(pts[p0 * 3 + 2], pts[p1 * 3 + 2]);

    const int f0 = blockIdx.y * FSEG;

    float best0 = CUDART_INF_F, best1 = CUDART_INF_F;
    int   bidx0 = f0,           bidx1 = f0;

    for (int t0 = 0; t0 < FSEG; t0 += TILE) {
        __syncthreads();
        {   // one triangle per thread: load, precompute invariants, double-pack
            const float* s = tb + (size_t)(f0 + t0 + tid) * 9;
            float ax = s[0], ay = s[1], az = s[2];
            float bx = s[3], by = s[4], bz = s[5];
            float cx = s[6], cy = s[7], cz = s[8];
            float abx = bx - ax, aby = by - ay, abz = bz - az;
            float acx = cx - ax, acy = cy - ay, acz = cz - az;
            float bcx = cx - bx, bcy = cy - by, bcz = cz - bz;
            float abab = fmaf(abx, abx, fmaf(aby, aby, abz * abz));
            float acac = fmaf(acx, acx, fmaf(acy, acy, acz * acz));
            float abac = fmaf(abx, acx, fmaf(aby, acy, abz * acz));
            float bcbc = fmaf(bcx, bcx, fmaf(bcy, bcy, bcz * bcz));
            float det  = fmaf(abab, acac, -abac * abac);
            float invdet  = 1.0f / ((det  == 0.0f) ? 1.0f : det);
            float invabab = 1.0f / ((abab == 0.0f) ? 1.0f : abab);
            float invacac = 1.0f / ((acac == 0.0f) ? 1.0f : acac);
            float invbcbc = 1.0f / ((bcbc == 0.0f) ? 1.0f : bcbc);

            ulonglong2* r = sT[tid];
            r[0]  = make_ulonglong2(PK(-ax, -ax), PK(-ay, -ay));
            r[1]  = make_ulonglong2(PK(-az, -az), PK(-bx, -bx));
            r[2]  = make_ulonglong2(PK(-by, -by), PK(-bz, -bz));
            r[3]  = make_ulonglong2(PK(abx, abx), PK(aby, aby));
            r[4]  = make_ulonglong2(PK(abz, abz), PK(acx, acx));
            r[5]  = make_ulonglong2(PK(acy, acy), PK(acz, acz));
            r[6]  = make_ulonglong2(PK(bcx, bcx), PK(bcy, bcy));
            r[7]  = make_ulonglong2(PK(bcz, bcz), PK(acac, acac));
            r[8]  = make_ulonglong2(PK(-abac, -abac), PK(abab, abab));
            r[9]  = make_ulonglong2(PK(invdet, invdet), PK(invabab, invabab));
            r[10] = make_ulonglong2(PK(invacac, invacac), PK(invbcbc, invbcbc));
            r[11] = make_ulonglong2(PK(det, det), 0ull);
        }
        __syncthreads();

        #pragma unroll 2
        for (int j = 0; j < TILE; ++j) {
            const ulonglong2* r = sT[j];
            const ulonglong2 L0 = r[0], L1 = r[1], L2 = r[2], L3 = r[3];
            const ulonglong2 L4 = r[4], L5 = r[5], L6 = r[6], L7 = r[7];
            const ulonglong2 L8 = r[8], L9 = r[9], L10 = r[10], L11 = r[11];

            const u64 abx = L3.x, aby = L3.y, abz = L4.x;
            const u64 acx = L4.y, acy = L5.x, acz = L5.y;
            const u64 bcx = L6.x, bcy = L6.y, bcz = L7.x;

            // ap = p - a, bp = p - b
            u64 apx = ADD2(ppx, L0.x), apy = ADD2(ppy, L0.y), apz = ADD2(ppz, L1.x);
            u64 bpx = ADD2(ppx, L1.y), bpy = ADD2(ppy, L2.x), bpz = ADD2(ppz, L2.y);

            u64 d1 = FMA2(abx, apx, FMA2(aby, apy, MUL2(abz, apz)));
            u64 d2 = FMA2(acx, apx, FMA2(acy, apy, MUL2(acz, apz)));
            u64 tn = FMA2(bcx, bpx, FMA2(bcy, bpy, MUL2(bcz, bpz)));  // = d4-d3

            // interior barycentrics
            u64 vb = FMA2(d1, L7.y, MUL2(L8.x, d2));   // acac*d1 - abac*d2
            u64 vc = FMA2(d2, L8.y, MUL2(L8.x, d1));   // abab*d2 - abac*d1
            u64 vI = MUL2(vb, L9.x);
            u64 wI = MUL2(vc, L9.x);

            // edge parameters, clamped
            u64 tab = CLAMP01_2(MUL2(d1, L9.y));
            u64 tac = CLAMP01_2(MUL2(d2, L10.x));
            u64 tbc = CLAMP01_2(MUL2(tn, L10.y));

            u64 napx = NEG2(apx), napy = NEG2(apy), napz = NEG2(apz);
            u64 nbpx = NEG2(bpx), nbpy = NEG2(bpy), nbpz = NEG2(bpz);

            // interior candidate: v*ab + w*ac - ap
            u64 ix = FMA2(vI, abx, FMA2(wI, acx, napx));
            u64 iy = FMA2(vI, aby, FMA2(wI, acy, napy));
            u64 iz = FMA2(vI, abz, FMA2(wI, acz, napz));
            u64 dI = FMA2(ix, ix, FMA2(iy, iy, MUL2(iz, iz)));

            // edge AB: t*ab - ap
            u64 ax_ = FMA2(tab, abx, napx);
            u64 ay_ = FMA2(tab, aby, napy);
            u64 az_ = FMA2(tab, abz, napz);
            u64 dA = FMA2(ax_, ax_, FMA2(ay_, ay_, MUL2(az_, az_)));

            // edge AC: t*ac - ap
            u64 cx_ = FMA2(tac, acx, napx);
            u64 cy_ = FMA2(tac, acy, napy);
            u64 cz_ = FMA2(tac, acz, napz);
            u64 dC = FMA2(cx_, cx_, FMA2(cy_, cy_, MUL2(cz_, cz_)));

            // edge BC: t*bc - bp
            u64 bx_ = FMA2(tbc, bcx, nbpx);
            u64 by_ = FMA2(tbc, bcy, nbpy);
            u64 bz_ = FMA2(tbc, bcz, nbpz);
            u64 dB = FMA2(bx_, bx_, FMA2(by_, by_, MUL2(bz_, bz_)));

            u64 svbc = ADD2(vb, vc);

            // scalar tail per point
            float vb0, vb1, vc0, vc1, sv0, sv1, det_s, dum;
            float dI0, dI1, dA0, dA1, dB0, dB1, dC0, dC1;
            UPK(vb, vb0, vb1); UPK(vc, vc0, vc1); UPK(svbc, sv0, sv1);
            UPK(L11.x, det_s, dum);
            UPK(dI, dI0, dI1); UPK(dA, dA0, dA1);
            UPK(dB, dB0, dB1); UPK(dC, dC0, dC1);

            const int fid = f0 + t0 + j;

            bool in0 = (vb0 >= 0.0f) & (vc0 >= 0.0f) & (sv0 <= det_s);
            float e0 = fminf(fminf(dA0, dC0), fminf(dB0, in0 ? dI0 : CUDART_INF_F));
            if (e0 < best0) { best0 = e0; bidx0 = fid; }

            bool in1 = (vb1 >= 0.0f) & (vc1 >= 0.0f) & (sv1 <= det_s);
            float e1 = fminf(fminf(dA1, dC1), fminf(dB1, in1 ? dI1 : CUDART_INF_F));
            if (e1 < best1) { best1 = e1; bidx1 = fid; }
        }
    }

    u64 k0 = ((u64)__float_as_uint(best0) << 32) | (u64)(unsigned)bidx0;
    u64 k1 = ((u64)__float_as_uint(best1) << 32) | (u64)(unsigned)bidx1;
    atomicMin(&g_key[p0], k0);
    atomicMin(&g_key[p1], k1);
}

// ---------------------------------------------------------------------------
// Kernel 2: read winning triangle, recompute exact reference bary, clamp,
// gather, write outputs.
// Output (float32): residual[8192*3] | normals[8192*3] | cmaps[8192*3] | idx[8192]
// ---------------------------------------------------------------------------
__global__ void p2m_finalize_kernel(
    const float* __restrict__ tri, const float* __restrict__ pts,
    const float* __restrict__ nrm, const float* __restrict__ cmp,
    const int*   __restrict__ faces, float* __restrict__ out)
{
    const int pid = blockIdx.x * blockDim.x + threadIdx.x;
    if (pid >= NPTS) return;

    const int bidx = (int)(g_key[pid] & 0xFFFFFFFFull);

    const int b = pid >> 12;
    const size_t fbase = (size_t)(b * FF + bidx);

    const float px = pts[pid * 3 + 0];
    const float py = pts[pid * 3 + 1];
    const float pz = pts[pid * 3 + 2];

    const float* t = tri + fbase * 9;
    float ax = t[0], ay = t[1], az = t[2];
    float bx = t[3], by = t[4], bz = t[5];
    float cx = t[6], cy = t[7], cz = t[8];

    float u, v, w;
    bary_uvw_exact(ax, ay, az, bx, by, bz, cx, cy, cz, px, py, pz, u, v, w);

    u = fminf(fmaxf(u, 0.0f), 1.0f);
    v = fminf(fmaxf(v, 0.0f), 1.0f);
    w = fminf(fmaxf(w, 0.0f), 1.0f);

    out[pid * 3 + 0] = (u * ax + v * bx + w * cx) - px;
    out[pid * 3 + 1] = (u * ay + v * by + w * cy) - py;
    out[pid * 3 + 2] = (u * az + v * bz + w * cz) - pz;

    const float* n = nrm + fbase * 9;
    out[NPTS * 3 + pid * 3 + 0] = u * n[0] + v * n[3] + w * n[6];
    out[NPTS * 3 + pid * 3 + 1] = u * n[1] + v * n[4] + w * n[7];
    out[NPTS * 3 + pid * 3 + 2] = u * n[2] + v * n[5] + w * n[8];

    const float* cm = cmp + fbase * 9;
    out[NPTS * 6 + pid * 3 + 0] = u * cm[0] + v * cm[3] + w * cm[6];
    out[NPTS * 6 + pid * 3 + 1] = u * cm[1] + v * cm[4] + w * cm[7];
    out[NPTS * 6 + pid * 3 + 2] = u * cm[2] + v * cm[5] + w * cm[8];

    int k = (u >= v && u >= w) ? 0 : ((v >= w) ? 1 : 2);
    out[NPTS * 9 + pid] = (float)faces[fbase * 3 + k];
}

extern "C" void kernel_launch(void* const* d_in, const int* in_sizes, int n_in,
                              void* d_out, int out_size)
{
    const float* tri   = (const float*)d_in[0];   // [B,F,3,3]
    const float* pts   = (const float*)d_in[1];   // [B,Q,3]
    const float* nrm   = (const float*)d_in[2];   // [B,F,3,3]
    const float* cmp   = (const float*)d_in[3];   // [B,F,3,3]
    const int*   faces = (const int*)  d_in[4];   // [B,F,3]
    float* out = (float*)d_out;

    p2m_init_kernel<<<NPTS / 256, 256>>>();
    dim3 grid1(NPTS / (BLK * PPT), NSPLIT);       // (32, 32)
    p2m_search_kernel<<<grid1, BLK>>>(tri, pts);
    p2m_finalize_kernel<<<NPTS / 256, 256>>>(tri, pts, nrm, cmp, faces, out);
}

// round 8
// speedup vs baseline: 3.2467x; 1.1325x over previous
#include <cuda_runtime.h>
#include <cuda_bf16.h>
#include <math_constants.h>

#define BB      2
#define FF      8192
#define QQ      4096
#define NPTS    (BB * QQ)        // 8192
#define NSPLIT  32
#define FSEG    (FF / NSPLIT)    // 256
#define TILE    128
#define BLK     128
#define PPT     2                // points per thread (f32x2 lanes)
#define NREC    13               // ulonglong2 per triangle record

typedef unsigned long long u64;

// Per-point argmin key: (float_bits(d2) << 32) | fid. atomicMin over unique
// keys is order-independent; smaller fid wins exact ties = first-occurrence.
__device__ u64 g_key[NPTS];

// ---------------------------------------------------------------------------
// f32x2 packed helpers (sm_103a)
// ---------------------------------------------------------------------------
__device__ __forceinline__ u64 PK(float lo, float hi) {
    u64 r; asm("mov.b64 %0, {%1, %2};" : "=l"(r) : "f"(lo), "f"(hi)); return r;
}
__device__ __forceinline__ void UPK(u64 p, float& lo, float& hi) {
    asm("mov.b64 {%0, %1}, %2;" : "=f"(lo), "=f"(hi) : "l"(p));
}
__device__ __forceinline__ u64 FMA2(u64 a, u64 b, u64 c) {
    u64 d; asm("fma.rn.f32x2 %0, %1, %2, %3;" : "=l"(d) : "l"(a), "l"(b), "l"(c)); return d;
}
__device__ __forceinline__ u64 ADD2(u64 a, u64 b) {
    u64 d; asm("add.rn.f32x2 %0, %1, %2;" : "=l"(d) : "l"(a), "l"(b)); return d;
}
__device__ __forceinline__ u64 MUL2(u64 a, u64 b) {
    u64 d; asm("mul.rn.f32x2 %0, %1, %2;" : "=l"(d) : "l"(a), "l"(b)); return d;
}
__device__ __forceinline__ u64 NEG2(u64 a) {   // ALU/LOP pipe sign flip
    u64 d; asm("xor.b64 %0, %1, 0x8000000080000000;" : "=l"(d) : "l"(a)); return d;
}

__device__ __forceinline__ float clamp01(float t) {
    return fminf(fmaxf(t, 0.0f), 1.0f);
}
__device__ __forceinline__ u64 CLAMP01_2(u64 t) {
    float lo, hi; UPK(t, lo, hi);
    return PK(clamp01(lo), clamp01(hi));
}

// ---------------------------------------------------------------------------
// Exact reference arithmetic (finalize only — produces the actual outputs).
// ---------------------------------------------------------------------------
__device__ __forceinline__ float safe_div(float n, float d) {
    return n / ((d == 0.0f) ? 1.0f : d);
}

__device__ __forceinline__ void bary_uvw_exact(
    float ax, float ay, float az,
    float bx, float by, float bz,
    float cx, float cy, float cz,
    float px, float py, float pz,
    float& u, float& v, float& w)
{
    float abx = bx - ax, aby = by - ay, abz = bz - az;
    float acx = cx - ax, acy = cy - ay, acz = cz - az;
    float apx = px - ax, apy = py - ay, apz = pz - az;
    float d1 = abx * apx + aby * apy + abz * apz;
    float d2 = acx * apx + acy * apy + acz * apz;
    float bpx = px - bx, bpy = py - by, bpz = pz - bz;
    float d3 = abx * bpx + aby * bpy + abz * bpz;
    float d4 = acx * bpx + acy * bpy + acz * bpz;
    float cpx = px - cx, cpy = py - cy, cpz = pz - cz;
    float d5 = abx * cpx + aby * cpy + abz * cpz;
    float d6 = acx * cpx + acy * cpy + acz * cpz;
    float vc = d1 * d4 - d3 * d2;
    float vb = d5 * d2 - d1 * d6;
    float va = d3 * d6 - d5 * d4;

    float inv = safe_div(1.0f, va + vb + vc);
    v = vb * inv;
    w = vc * inv;

    if (va <= 0.0f && d4 >= d3 && d5 >= d6) {
        float num = d4 - d3;
        float wbc = safe_div(num, num + (d5 - d6));
        v = 1.0f - wbc; w = wbc;
    }
    if (vb <= 0.0f && d2 >= 0.0f && d6 <= 0.0f) {
        v = 0.0f; w = safe_div(d2, d2 - d6);
    }
    if (d6 >= 0.0f && d5 <= d6) { v = 0.0f; w = 1.0f; }
    if (vc <= 0.0f && d1 >= 0.0f && d3 <= 0.0f) {
        v = safe_div(d1, d1 - d3); w = 0.0f;
    }
    if (d3 >= 0.0f && d4 <= d3) { v = 1.0f; w = 0.0f; }
    if (d1 <= 0.0f && d2 <= 0.0f) { v = 0.0f; w = 0.0f; }

    u = 1.0f - v - w;
}

// ---------------------------------------------------------------------------
// Kernel 0: reset argmin keys (graph-replay safe).
// ---------------------------------------------------------------------------
__global__ void p2m_init_kernel() {
    int i = blockIdx.x * blockDim.x + threadIdx.x;
    if (i < NPTS) g_key[i] = ~0ull;
}

// ---------------------------------------------------------------------------
// Kernel 1: brute-force argmin search, f32x2-packed, 2 points/thread.
//
// Per-triangle smem record: 26 packed-doubled u64 = 13 ulonglong2 (208 B):
//   r0 (-ax,-ay)  r1 (-az,-bx)  r2 (-by,-bz)
//   r3 (abx,aby)  r4 (abz,acx)  r5 (acy,acz)
//   r6 (bcx,bcy)  r7 (bcz,acac) r8 (-abac,abab)
//   r9 (invabab,invacac)  r10 (invbcbc,-abbc)
//   r11 (nsx,nsy) r12 (nsz,det)            ns = (ab x ac) * rsqrt(det)
//
// Candidates:
//   interior: dI = (ns . ap)^2, masked by vb>=0 && vc>=0 && vb+vc<=det
//             (valid: |ab x ac|^2 = abab*acac - abac^2 = det, and inside the
//              mask the point-triangle distance IS the plane distance)
//   edge AB:  |ap - clamp01(d1*invabab)*ab|^2      (vector form, eps-relative)
//   edge AC:  |ap - clamp01(d2*invacac)*ac|^2
//   edge BC:  |bp - clamp01(tn*invbcbc)*bc|^2,  tn = (d2-d1) - ab.bc = bc.bp
// min of candidates == exact Ericson distance.
// ---------------------------------------------------------------------------
__global__ void __launch_bounds__(BLK)
p2m_search_kernel(const float* __restrict__ tri, const float* __restrict__ pts)
{
    __shared__ ulonglong2 sT[TILE][NREC];

    const int tid = threadIdx.x;
    const int p0  = blockIdx.x * (BLK * PPT) + tid;
    const int p1  = p0 + BLK;               // same 256-group -> same batch
    const int b   = p0 >> 12;               // Q = 4096
    const float* tb = tri + (size_t)b * FF * 9;

    const u64 ppx = PK(pts[p0 * 3 + 0], pts[p1 * 3 + 0]);
    const u64 ppy = PK(pts[p0 * 3 + 1], pts[p1 * 3 + 1]);
    const u64 ppz = PK(pts[p0 * 3 + 2], pts[p1 * 3 + 2]);

    const int f0 = blockIdx.y * FSEG;

    float best0 = CUDART_INF_F, best1 = CUDART_INF_F;
    int   bidx0 = f0,           bidx1 = f0;

    for (int t0 = 0; t0 < FSEG; t0 += TILE) {
        __syncthreads();
        {   // one triangle per thread: load, precompute invariants, double-pack
            const float* s = tb + (size_t)(f0 + t0 + tid) * 9;
            float ax = s[0], ay = s[1], az = s[2];
            float bx = s[3], by = s[4], bz = s[5];
            float cx = s[6], cy = s[7], cz = s[8];
            float abx = bx - ax, aby = by - ay, abz = bz - az;
            float acx = cx - ax, acy = cy - ay, acz = cz - az;
            float bcx = cx - bx, bcy = cy - by, bcz = cz - bz;
            float abab = fmaf(abx, abx, fmaf(aby, aby, abz * abz));
            float acac = fmaf(acx, acx, fmaf(acy, acy, acz * acz));
            float abac = fmaf(abx, acx, fmaf(aby, acy, abz * acz));
            float bcbc = fmaf(bcx, bcx, fmaf(bcy, bcy, bcz * bcz));
            float abbc = fmaf(abx, bcx, fmaf(aby, bcy, abz * bcz));
            float det  = fmaf(abab, acac, -abac * abac);
            // unnormalized normal n = ab x ac; |n|^2 == det
            float nx = fmaf(aby, acz, -abz * acy);
            float ny = fmaf(abz, acx, -abx * acz);
            float nz = fmaf(abx, acy, -aby * acx);
            float rs = rsqrtf((det == 0.0f) ? 1.0f : det);
            float nsx = nx * rs, nsy = ny * rs, nsz = nz * rs;
            float invabab = 1.0f / ((abab == 0.0f) ? 1.0f : abab);
            float invacac = 1.0f / ((acac == 0.0f) ? 1.0f : acac);
            float invbcbc = 1.0f / ((bcbc == 0.0f) ? 1.0f : bcbc);

            ulonglong2* r = sT[tid];
            r[0]  = make_ulonglong2(PK(-ax, -ax), PK(-ay, -ay));
            r[1]  = make_ulonglong2(PK(-az, -az), PK(-bx, -bx));
            r[2]  = make_ulonglong2(PK(-by, -by), PK(-bz, -bz));
            r[3]  = make_ulonglong2(PK(abx, abx), PK(aby, aby));
            r[4]  = make_ulonglong2(PK(abz, abz), PK(acx, acx));
            r[5]  = make_ulonglong2(PK(acy, acy), PK(acz, acz));
            r[6]  = make_ulonglong2(PK(bcx, bcx), PK(bcy, bcy));
            r[7]  = make_ulonglong2(PK(bcz, bcz), PK(acac, acac));
            r[8]  = make_ulonglong2(PK(-abac, -abac), PK(abab, abab));
            r[9]  = make_ulonglong2(PK(invabab, invabab), PK(invacac, invacac));
            r[10] = make_ulonglong2(PK(invbcbc, invbcbc), PK(-abbc, -abbc));
            r[11] = make_ulonglong2(PK(nsx, nsx), PK(nsy, nsy));
            r[12] = make_ulonglong2(PK(nsz, nsz), PK(det, det));
        }
        __syncthreads();

        #pragma unroll 2
        for (int j = 0; j < TILE; ++j) {
            const ulonglong2* r = sT[j];
            const ulonglong2 L0 = r[0], L1 = r[1], L2 = r[2], L3 = r[3];
            const ulonglong2 L4 = r[4], L5 = r[5], L6 = r[6], L7 = r[7];
            const ulonglong2 L8 = r[8], L9 = r[9], L10 = r[10];
            const ulonglong2 L11 = r[11], L12 = r[12];

            // ap = p - a, bp = p - b
            u64 apx = ADD2(ppx, L0.x), apy = ADD2(ppy, L0.y), apz = ADD2(ppz, L1.x);
            u64 bpx = ADD2(ppx, L1.y), bpy = ADD2(ppy, L2.x), bpz = ADD2(ppz, L2.y);

            u64 d1 = FMA2(L3.x, apx, FMA2(L3.y, apy, MUL2(L4.x, apz)));
            u64 d2 = FMA2(L4.y, apx, FMA2(L5.x, apy, MUL2(L5.y, apz)));
            u64 nd = FMA2(L11.x, apx, FMA2(L11.y, apy, MUL2(L12.x, apz)));
            u64 tn = ADD2(ADD2(d2, NEG2(d1)), L10.y);   // bc.bp = (d2-d1) - ab.bc

            // interior mask ingredients
            u64 vb = FMA2(d1, L7.y, MUL2(L8.x, d2));    // acac*d1 - abac*d2
            u64 vc = FMA2(d2, L8.y, MUL2(L8.x, d1));    // abab*d2 - abac*d1
            u64 svbc = ADD2(vb, vc);
            u64 dI = MUL2(nd, nd);                      // plane distance^2

            // clamped edge parameters, negated
            u64 ntab = NEG2(CLAMP01_2(MUL2(d1, L9.x)));
            u64 ntac = NEG2(CLAMP01_2(MUL2(d2, L9.y)));
            u64 ntbc = NEG2(CLAMP01_2(MUL2(tn, L10.x)));

            // edge AB: ap - t*ab
            u64 ex = FMA2(ntab, L3.x, apx);
            u64 ey = FMA2(ntab, L3.y, apy);
            u64 ez = FMA2(ntab, L4.x, apz);
            u64 dA = FMA2(ex, ex, FMA2(ey, ey, MUL2(ez, ez)));

            // edge AC: ap - t*ac
            u64 fx = FMA2(ntac, L4.y, apx);
            u64 fy = FMA2(ntac, L5.x, apy);
            u64 fz = FMA2(ntac, L5.y, apz);
            u64 dC = FMA2(fx, fx, FMA2(fy, fy, MUL2(fz, fz)));

            // edge BC: bp - t*bc
            u64 gx = FMA2(ntbc, L6.x, bpx);
            u64 gy = FMA2(ntbc, L6.y, bpy);
            u64 gz = FMA2(ntbc, L7.x, bpz);
            u64 dB = FMA2(gx, gx, FMA2(gy, gy, MUL2(gz, gz)));

            // scalar tail per point
            float vb0, vb1, vc0, vc1, sv0, sv1, det_s, dum;
            float dI0, dI1, dA0, dA1, dB0, dB1, dC0, dC1;
            UPK(vb, vb0, vb1); UPK(vc, vc0, vc1); UPK(svbc, sv0, sv1);
            UPK(L12.y, det_s, dum);
            UPK(dI, dI0, dI1); UPK(dA, dA0, dA1);
            UPK(dB, dB0, dB1); UPK(dC, dC0, dC1);

            const int fid = f0 + t0 + j;

            bool in0 = (vb0 >= 0.0f) & (vc0 >= 0.0f) & (sv0 <= det_s);
            float e0 = fminf(fminf(dA0, dC0), fminf(dB0, in0 ? dI0 : CUDART_INF_F));
            if (e0 < best0) { best0 = e0; bidx0 = fid; }

            bool in1 = (vb1 >= 0.0f) & (vc1 >= 0.0f) & (sv1 <= det_s);
            float e1 = fminf(fminf(dA1, dC1), fminf(dB1, in1 ? dI1 : CUDART_INF_F));
            if (e1 < best1) { best1 = e1; bidx1 = fid; }
        }
    }

    u64 k0 = ((u64)__float_as_uint(best0) << 32) | (u64)(unsigned)bidx0;
    u64 k1 = ((u64)__float_as_uint(best1) << 32) | (u64)(unsigned)bidx1;
    atomicMin(&g_key[p0], k0);
    atomicMin(&g_key[p1], k1);
}

// ---------------------------------------------------------------------------
// Kernel 2: read winning triangle, recompute exact reference bary, clamp,
// gather, write outputs.
// Output (float32): residual[8192*3] | normals[8192*3] | cmaps[8192*3] | idx[8192]
// ---------------------------------------------------------------------------
__global__ void p2m_finalize_kernel(
    const float* __restrict__ tri, const float* __restrict__ pts,
    const float* __restrict__ nrm, const float* __restrict__ cmp,
    const int*   __restrict__ faces, float* __restrict__ out)
{
    const int pid = blockIdx.x * blockDim.x + threadIdx.x;
    if (pid >= NPTS) return;

    const int bidx = (int)(g_key[pid] & 0xFFFFFFFFull);

    const int b = pid >> 12;
    const size_t fbase = (size_t)(b * FF + bidx);

    const float px = pts[pid * 3 + 0];
    const float py = pts[pid * 3 + 1];
    const float pz = pts[pid * 3 + 2];

    const float* t = tri + fbase * 9;
    float ax = t[0], ay = t[1], az = t[2];
    float bx = t[3], by = t[4], bz = t[5];
    float cx = t[6], cy = t[7], cz = t[8];

    float u, v, w;
    bary_uvw_exact(ax, ay, az, bx, by, bz, cx, cy, cz, px, py, pz, u, v, w);

    u = fminf(fmaxf(u, 0.0f), 1.0f);
    v = fminf(fmaxf(v, 0.0f), 1.0f);
    w = fminf(fmaxf(w, 0.0f), 1.0f);

    out[pid * 3 + 0] = (u * ax + v * bx + w * cx) - px;
    out[pid * 3 + 1] = (u * ay + v * by + w * cy) - py;
    out[pid * 3 + 2] = (u * az + v * bz + w * cz) - pz;

    const float* n = nrm + fbase * 9;
    out[NPTS * 3 + pid * 3 + 0] = u * n[0] + v * n[3] + w * n[6];
    out[NPTS * 3 + pid * 3 + 1] = u * n[1] + v * n[4] + w * n[7];
    out[NPTS * 3 + pid * 3 + 2] = u * n[2] + v * n[5] + w * n[8];

    const float* cm = cmp + fbase * 9;
    out[NPTS * 6 + pid * 3 + 0] = u * cm[0] + v * cm[3] + w * cm[6];
    out[NPTS * 6 + pid * 3 + 1] = u * cm[1] + v * cm[4] + w * cm[7];
    out[NPTS * 6 + pid * 3 + 2] = u * cm[2] + v * cm[5] + w * cm[8];

    int k = (u >= v && u >= w) ? 0 : ((v >= w) ? 1 : 2);
    out[NPTS * 9 + pid] = (float)faces[fbase * 3 + k];
}

extern "C" void kernel_launch(void* const* d_in, const int* in_sizes, int n_in,
                              void* d_out, int out_size)
{
    const float* tri   = (const float*)d_in[0];   // [B,F,3,3]
    const float* pts   = (const float*)d_in[1];   // [B,Q,3]
    const float* nrm   = (const float*)d_in[2];   // [B,F,3,3]
    const float* cmp   = (const float*)d_in[3];   // [B,F,3,3]
    const int*   faces = (const int*)  d_in[4];   // [B,F,3]
    float* out = (float*)d_out;

    p2m_init_kernel<<<NPTS / 256, 256>>>();
    dim3 grid1(NPTS / (BLK * PPT), NSPLIT);       // (32, 32)
    p2m_search_kernel<<<grid1, BLK>>>(tri, pts);
    p2m_finalize_kernel<<<NPTS / 256, 256>>>(tri, pts, nrm, cmp, faces, out);
}

// round 9
// speedup vs baseline: 4.2312x; 1.3032x over previous
#include <cuda_runtime.h>
#include <cuda_bf16.h>
#include <math_constants.h>

#define BB      2
#define FF      8192
#define QQ      4096
#define NPTS    (BB * QQ)        // 8192
#define NSPLIT  32
#define FSEG    (FF / NSPLIT)    // 256
#define TILE    128
#define BLK     128
#define PPT     2                // points per thread (f32x2 lanes)
#define NREC    11               // ulonglong2 per triangle record

typedef unsigned long long u64;

// Per-point argmin: stores ~key where key = (float_bits(d2)<<32) | fid.
// atomicMax(~key) == min(key); zero-init (= ~(+inf,all-ones)) is the identity,
// so no init kernel is needed. Finalize resets slots to 0 after reading
// (graph-replay deterministic). Smaller fid wins exact d2 ties = first-occurrence.
__device__ u64 g_key[NPTS];   // static zero-init

// ---------------------------------------------------------------------------
// f32x2 packed helpers (sm_103a)
// ---------------------------------------------------------------------------
__device__ __forceinline__ u64 PK(float lo, float hi) {
    u64 r; asm("mov.b64 %0, {%1, %2};" : "=l"(r) : "f"(lo), "f"(hi)); return r;
}
__device__ __forceinline__ void UPK(u64 p, float& lo, float& hi) {
    asm("mov.b64 {%0, %1}, %2;" : "=f"(lo), "=f"(hi) : "l"(p));
}
__device__ __forceinline__ u64 FMA2(u64 a, u64 b, u64 c) {
    u64 d; asm("fma.rn.f32x2 %0, %1, %2, %3;" : "=l"(d) : "l"(a), "l"(b), "l"(c)); return d;
}
__device__ __forceinline__ u64 ADD2(u64 a, u64 b) {
    u64 d; asm("add.rn.f32x2 %0, %1, %2;" : "=l"(d) : "l"(a), "l"(b)); return d;
}
__device__ __forceinline__ u64 MUL2(u64 a, u64 b) {
    u64 d; asm("mul.rn.f32x2 %0, %1, %2;" : "=l"(d) : "l"(a), "l"(b)); return d;
}

__device__ __forceinline__ float clamp01(float t) {
    return fminf(fmaxf(t, 0.0f), 1.0f);
}
__device__ __forceinline__ u64 CLAMP01_2(u64 t) {
    float lo, hi; UPK(t, lo, hi);
    return PK(clamp01(lo), clamp01(hi));
}

// ---------------------------------------------------------------------------
// Exact reference arithmetic (finalize only — produces the actual outputs).
// ---------------------------------------------------------------------------
__device__ __forceinline__ float safe_div(float n, float d) {
    return n / ((d == 0.0f) ? 1.0f : d);
}

__device__ __forceinline__ void bary_uvw_exact(
    float ax, float ay, float az,
    float bx, float by, float bz,
    float cx, float cy, float cz,
    float px, float py, float pz,
    float& u, float& v, float& w)
{
    float abx = bx - ax, aby = by - ay, abz = bz - az;
    float acx = cx - ax, acy = cy - ay, acz = cz - az;
    float apx = px - ax, apy = py - ay, apz = pz - az;
    float d1 = abx * apx + aby * apy + abz * apz;
    float d2 = acx * apx + acy * apy + acz * apz;
    float bpx = px - bx, bpy = py - by, bpz = pz - bz;
    float d3 = abx * bpx + aby * bpy + abz * bpz;
    float d4 = acx * bpx + acy * bpy + acz * bpz;
    float cpx = px - cx, cpy = py - cy, cpz = pz - cz;
    float d5 = abx * cpx + aby * cpy + abz * cpz;
    float d6 = acx * cpx + acy * cpy + acz * cpz;
    float vc = d1 * d4 - d3 * d2;
    float vb = d5 * d2 - d1 * d6;
    float va = d3 * d6 - d5 * d4;

    float inv = safe_div(1.0f, va + vb + vc);
    v = vb * inv;
    w = vc * inv;

    if (va <= 0.0f && d4 >= d3 && d5 >= d6) {
        float num = d4 - d3;
        float wbc = safe_div(num, num + (d5 - d6));
        v = 1.0f - wbc; w = wbc;
    }
    if (vb <= 0.0f && d2 >= 0.0f && d6 <= 0.0f) {
        v = 0.0f; w = safe_div(d2, d2 - d6);
    }
    if (d6 >= 0.0f && d5 <= d6) { v = 0.0f; w = 1.0f; }
    if (vc <= 0.0f && d1 >= 0.0f && d3 <= 0.0f) {
        v = safe_div(d1, d1 - d3); w = 0.0f;
    }
    if (d3 >= 0.0f && d4 <= d3) { v = 1.0f; w = 0.0f; }
    if (d1 <= 0.0f && d2 <= 0.0f) { v = 0.0f; w = 0.0f; }

    u = 1.0f - v - w;
}

// ---------------------------------------------------------------------------
// Kernel 1: brute-force argmin search, 2D-frame formulation, f32x2-packed,
// 2 points/thread.
//
// Per-triangle precompute: orthonormal frame e1 = ab/|ab|, e2 = perp(ac)/|.|,
// n = e1 x e2. 2D verts: A=(0,0), B=(b1,0), C=(c1,c2) with c2 >= 0.
// Point -> (x, y, h) = (e1.ap, e2.ap, n.ap).
// True d^2 = h^2 + d2D^2 where d2D = 0 if (x,y) inside triangle, else min of
// the three 2D segment distances. Equals Ericson distance exactly in real
// arithmetic; rounding deviations are eps-relative in the residual components.
//
// smem record: 22 packed-doubled u64 = 11 ulonglong2 (176 B):
//   r0 (-ax,-ay)  r1 (-az,e1x)  r2 (e1y,e1z)  r3 (e2x,e2y)  r4 (e2z,nx)
//   r5 (ny,nz)    r6 (-b1,cs1)  r7 (cs2,-c1)  r8 (-c2,bcs1) r9 (bcs2,-bcx)
//   r10 (bcx,c2)          cs = (c1,c2)/acac, bcs = (bcx,c2)/bcbc, bcx = c1-b1
// ---------------------------------------------------------------------------
__global__ void __launch_bounds__(BLK)
p2m_search_kernel(const float* __restrict__ tri, const float* __restrict__ pts)
{
    __shared__ ulonglong2 sT[TILE][NREC];

    const int tid = threadIdx.x;
    const int p0  = blockIdx.x * (BLK * PPT) + tid;
    const int p1  = p0 + BLK;               // same 256-group -> same batch
    const int b   = p0 >> 12;               // Q = 4096
    const float* tb = tri + (size_t)b * FF * 9;

    const u64 ppx = PK(pts[p0 * 3 + 0], pts[p1 * 3 + 0]);
    const u64 ppy = PK(pts[p0 * 3 + 1], pts[p1 * 3 + 1]);
    const u64 ppz = PK(pts[p0 * 3 + 2], pts[p1 * 3 + 2]);

    const int f0 = blockIdx.y * FSEG;

    float best0 = CUDART_INF_F, best1 = CUDART_INF_F;
    int   bidx0 = f0,           bidx1 = f0;

    for (int t0 = 0; t0 < FSEG; t0 += TILE) {
        __syncthreads();
        {   // one triangle per thread: build 2D frame record
            const float* s = tb + (size_t)(f0 + t0 + tid) * 9;
            float ax = s[0], ay = s[1], az = s[2];
            float bx = s[3], by = s[4], bz = s[5];
            float cx = s[6], cy = s[7], cz = s[8];
            float abx = bx - ax, aby = by - ay, abz = bz - az;
            float acx = cx - ax, acy = cy - ay, acz = cz - az;
            float abab = fmaf(abx, abx, fmaf(aby, aby, abz * abz));
            float acac = fmaf(acx, acx, fmaf(acy, acy, acz * acz));
            float abac = fmaf(abx, acx, fmaf(aby, acy, abz * acz));

            float rs1 = rsqrtf((abab == 0.0f) ? 1.0f : abab);
            float e1x = abx * rs1, e1y = aby * rs1, e1z = abz * rs1;
            float b1  = abab * rs1;                 // |ab|
            float c1  = abac * rs1;                 // ac . e1
            // perpendicular part of ac
            float qx = fmaf(-c1, e1x, acx);
            float qy = fmaf(-c1, e1y, acy);
            float qz = fmaf(-c1, e1z, acz);
            float qq = fmaf(qx, qx, fmaf(qy, qy, qz * qz));
            float rs2 = rsqrtf((qq == 0.0f) ? 1.0f : qq);
            float e2x = qx * rs2, e2y = qy * rs2, e2z = qz * rs2;
            float c2  = qq * rs2;                   // >= 0
            float nx = fmaf(e1y, e2z, -e1z * e2y);
            float ny = fmaf(e1z, e2x, -e1x * e2z);
            float nz = fmaf(e1x, e2y, -e1y * e2x);

            float invcc = 1.0f / ((acac == 0.0f) ? 1.0f : acac);
            float cs1 = c1 * invcc, cs2 = c2 * invcc;
            float bcx = c1 - b1;                    // bc in 2D = (bcx, c2)
            float bcbc = fmaf(bcx, bcx, c2 * c2);
            float invbc = 1.0f / ((bcbc == 0.0f) ? 1.0f : bcbc);
            float bcs1 = bcx * invbc, bcs2 = c2 * invbc;

            ulonglong2* r = sT[tid];
            r[0]  = make_ulonglong2(PK(-ax, -ax),   PK(-ay, -ay));
            r[1]  = make_ulonglong2(PK(-az, -az),   PK(e1x, e1x));
            r[2]  = make_ulonglong2(PK(e1y, e1y),   PK(e1z, e1z));
            r[3]  = make_ulonglong2(PK(e2x, e2x),   PK(e2y, e2y));
            r[4]  = make_ulonglong2(PK(e2z, e2z),   PK(nx, nx));
            r[5]  = make_ulonglong2(PK(ny, ny),     PK(nz, nz));
            r[6]  = make_ulonglong2(PK(-b1, -b1),   PK(cs1, cs1));
            r[7]  = make_ulonglong2(PK(cs2, cs2),   PK(-c1, -c1));
            r[8]  = make_ulonglong2(PK(-c2, -c2),   PK(bcs1, bcs1));
            r[9]  = make_ulonglong2(PK(bcs2, bcs2), PK(-bcx, -bcx));
            r[10] = make_ulonglong2(PK(bcx, bcx),   PK(c2, c2));
        }
        __syncthreads();

        #pragma unroll 2
        for (int j = 0; j < TILE; ++j) {
            const ulonglong2* r = sT[j];
            const ulonglong2 L0 = r[0], L1 = r[1], L2 = r[2], L3 = r[3];
            const ulonglong2 L4 = r[4], L5 = r[5], L6 = r[6], L7 = r[7];
            const ulonglong2 L8 = r[8], L9 = r[9], L10 = r[10];

            // ap = p - a
            u64 apx = ADD2(ppx, L0.x), apy = ADD2(ppy, L0.y), apz = ADD2(ppz, L1.x);

            // frame coordinates
            u64 x = FMA2(L1.y, apx, FMA2(L2.x, apy, MUL2(L2.y, apz)));
            u64 y = FMA2(L3.x, apx, FMA2(L3.y, apy, MUL2(L4.x, apz)));
            u64 h = FMA2(L4.y, apx, FMA2(L5.x, apy, MUL2(L5.y, apz)));

            u64 xb = ADD2(x, L6.x);            // x - b1

            // edge AB (on x-axis): dx = max(x-b1, min(x,0)); d = dx^2 + y^2
            float x0, x1, xb0, xb1;
            UPK(x, x0, x1); UPK(xb, xb0, xb1);
            u64 dxab = PK(fmaxf(xb0, fminf(x0, 0.0f)),
                          fmaxf(xb1, fminf(x1, 0.0f)));
            u64 y2  = MUL2(y, y);
            u64 dAB = FMA2(dxab, dxab, y2);

            // edge CA (A->C): t = clamp01(x*cs1 + y*cs2); d = (x-t*c1)^2 + (y-t*c2)^2
            u64 tca = CLAMP01_2(FMA2(x, L6.y, MUL2(y, L7.x)));
            u64 dxc = FMA2(tca, L7.y, x);
            u64 dyc = FMA2(tca, L8.x, y);
            u64 dCA = FMA2(dxc, dxc, MUL2(dyc, dyc));

            // edge BC (B->C): t = clamp01(xb*bcs1 + y*bcs2); d = (xb-t*bcx)^2 + (y-t*c2)^2
            u64 tbc = CLAMP01_2(FMA2(xb, L8.y, MUL2(y, L9.x)));
            u64 dxb = FMA2(tbc, L9.y, xb);
            u64 dyb = FMA2(tbc, L8.x, y);
            u64 dBC = FMA2(dxb, dxb, MUL2(dyb, dyb));

            // interior sign tests: y>=0, s1 = c2*x - c1*y >= 0, s2 = bcx*y - c2*xb >= 0
            u64 s1 = FMA2(L10.y, x, MUL2(L7.y, y));    // c2*x + (-c1)*y
            u64 s2 = FMA2(L10.x, y, MUL2(L8.x, xb));   // bcx*y + (-c2)*xb

            // scalar tail per point
            float yy0, yy1, s10, s11, s20, s21;
            float dA0, dA1, dC0, dC1, dB0, dB1, h0, h1;
            UPK(y, yy0, yy1); UPK(s1, s10, s11); UPK(s2, s20, s21);
            UPK(dAB, dA0, dA1); UPK(dCA, dC0, dC1); UPK(dBC, dB0, dB1);
            UPK(h, h0, h1);

            bool in0 = (yy0 >= 0.0f) & (s10 >= 0.0f) & (s20 >= 0.0f);
            bool in1 = (yy1 >= 0.0f) & (s11 >= 0.0f) & (s21 >= 0.0f);
            float m0 = in0 ? 0.0f : fminf(fminf(dA0, dC0), dB0);
            float m1 = in1 ? 0.0f : fminf(fminf(dA1, dC1), dB1);

            u64 dist = FMA2(h, h, PK(m0, m1));
            float e0, e1;
            UPK(dist, e0, e1);

            const int fid = f0 + t0 + j;
            if (e0 < best0) { best0 = e0; bidx0 = fid; }
            if (e1 < best1) { best1 = e1; bidx1 = fid; }
        }
    }

    u64 k0 = ((u64)__float_as_uint(best0) << 32) | (u64)(unsigned)bidx0;
    u64 k1 = ((u64)__float_as_uint(best1) << 32) | (u64)(unsigned)bidx1;
    atomicMax(&g_key[p0], ~k0);
    atomicMax(&g_key[p1], ~k1);
}

// ---------------------------------------------------------------------------
// Kernel 2: read winning triangle (complemented key), reset slot for next
// graph replay, recompute exact reference bary, clamp, gather, write outputs.
// Output (float32): residual[8192*3] | normals[8192*3] | cmaps[8192*3] | idx[8192]
// ---------------------------------------------------------------------------
__global__ void p2m_finalize_kernel(
    const float* __restrict__ tri, const float* __restrict__ pts,
    const float* __restrict__ nrm, const float* __restrict__ cmp,
    const int*   __restrict__ faces, float* __restrict__ out)
{
    const int pid = blockIdx.x * blockDim.x + threadIdx.x;
    if (pid >= NPTS) return;

    const u64 raw = g_key[pid];
    g_key[pid] = 0ull;                         // reset for next replay
    const int bidx = (int)((~raw) & 0xFFFFFFFFull);

    const int b = pid >> 12;
    const size_t fbase = (size_t)(b * FF + bidx);

    const float px = pts[pid * 3 + 0];
    const float py = pts[pid * 3 + 1];
    const float pz = pts[pid * 3 + 2];

    const float* t = tri + fbase * 9;
    float ax = t[0], ay = t[1], az = t[2];
    float bx = t[3], by = t[4], bz = t[5];
    float cx = t[6], cy = t[7], cz = t[8];

    float u, v, w;
    bary_uvw_exact(ax, ay, az, bx, by, bz, cx, cy, cz, px, py, pz, u, v, w);

    u = fminf(fmaxf(u, 0.0f), 1.0f);
    v = fminf(fmaxf(v, 0.0f), 1.0f);
    w = fminf(fmaxf(w, 0.0f), 1.0f);

    out[pid * 3 + 0] = (u * ax + v * bx + w * cx) - px;
    out[pid * 3 + 1] = (u * ay + v * by + w * cy) - py;
    out[pid * 3 + 2] = (u * az + v * bz + w * cz) - pz;

    const float* n = nrm + fbase * 9;
    out[NPTS * 3 + pid * 3 + 0] = u * n[0] + v * n[3] + w * n[6];
    out[NPTS * 3 + pid * 3 + 1] = u * n[1] + v * n[4] + w * n[7];
    out[NPTS * 3 + pid * 3 + 2] = u * n[2] + v * n[5] + w * n[8];

    const float* cm = cmp + fbase * 9;
    out[NPTS * 6 + pid * 3 + 0] = u * cm[0] + v * cm[3] + w * cm[6];
    out[NPTS * 6 + pid * 3 + 1] = u * cm[1] + v * cm[4] + w * cm[7];
    out[NPTS * 6 + pid * 3 + 2] = u * cm[2] + v * cm[5] + w * cm[8];

    int k = (u >= v && u >= w) ? 0 : ((v >= w) ? 1 : 2);
    out[NPTS * 9 + pid] = (float)faces[fbase * 3 + k];
}

extern "C" void kernel_launch(void* const* d_in, const int* in_sizes, int n_in,
                              void* d_out, int out_size)
{
    const float* tri   = (const float*)d_in[0];   // [B,F,3,3]
    const float* pts   = (const float*)d_in[1];   // [B,Q,3]
    const float* nrm   = (const float*)d_in[2];   // [B,F,3,3]
    const float* cmp   = (const float*)d_in[3];   // [B,F,3,3]
    const int*   faces = (const int*)  d_in[4];   // [B,F,3]
    float* out = (float*)d_out;

    dim3 grid1(NPTS / (BLK * PPT), NSPLIT);       // (32, 32)
    p2m_search_kernel<<<grid1, BLK>>>(tri, pts);
    p2m_finalize_kernel<<<NPTS / 256, 256>>>(tri, pts, nrm, cmp, faces, out);
}

// round 10
// speedup vs baseline: 4.6557x; 1.1003x over previous
#include <cuda_runtime.h>
#include <cuda_bf16.h>
#include <math_constants.h>

#define BB      2
#define FF      8192
#define QQ      4096
#define NPTS    (BB * QQ)        // 8192
#define NSPLIT  64
#define FSEG    (FF / NSPLIT)    // 128
#define TILE    128              // == FSEG: single-tile blocks
#define BLK     128
#define PPT     4                // points per thread (2 f32x2 pairs)
#define NREC    11               // ulonglong2 per triangle record

typedef unsigned long long u64;

// Per-point argmin: stores ~key where key = (float_bits(d2)<<32) | fid.
// atomicMax(~key) == min(key); zero-init is the identity, so no init kernel.
// Finalize resets slots to 0 after reading (graph-replay deterministic).
// Smaller fid wins exact d2 ties = first-occurrence argmin.
__device__ u64 g_key[NPTS];   // static zero-init

// ---------------------------------------------------------------------------
// f32x2 packed helpers (sm_103a)
// ---------------------------------------------------------------------------
__device__ __forceinline__ u64 PK(float lo, float hi) {
    u64 r; asm("mov.b64 %0, {%1, %2};" : "=l"(r) : "f"(lo), "f"(hi)); return r;
}
__device__ __forceinline__ void UPK(u64 p, float& lo, float& hi) {
    asm("mov.b64 {%0, %1}, %2;" : "=f"(lo), "=f"(hi) : "l"(p));
}
__device__ __forceinline__ u64 FMA2(u64 a, u64 b, u64 c) {
    u64 d; asm("fma.rn.f32x2 %0, %1, %2, %3;" : "=l"(d) : "l"(a), "l"(b), "l"(c)); return d;
}
__device__ __forceinline__ u64 ADD2(u64 a, u64 b) {
    u64 d; asm("add.rn.f32x2 %0, %1, %2;" : "=l"(d) : "l"(a), "l"(b)); return d;
}
__device__ __forceinline__ u64 MUL2(u64 a, u64 b) {
    u64 d; asm("mul.rn.f32x2 %0, %1, %2;" : "=l"(d) : "l"(a), "l"(b)); return d;
}

__device__ __forceinline__ float clamp01(float t) {
    return fminf(fmaxf(t, 0.0f), 1.0f);
}
__device__ __forceinline__ u64 CLAMP01_2(u64 t) {
    float lo, hi; UPK(t, lo, hi);
    return PK(clamp01(lo), clamp01(hi));
}

// ---------------------------------------------------------------------------
// Exact reference arithmetic (finalize only — produces the actual outputs).
// ---------------------------------------------------------------------------
__device__ __forceinline__ float safe_div(float n, float d) {
    return n / ((d == 0.0f) ? 1.0f : d);
}

__device__ __forceinline__ void bary_uvw_exact(
    float ax, float ay, float az,
    float bx, float by, float bz,
    float cx, float cy, float cz,
    float px, float py, float pz,
    float& u, float& v, float& w)
{
    float abx = bx - ax, aby = by - ay, abz = bz - az;
    float acx = cx - ax, acy = cy - ay, acz = cz - az;
    float apx = px - ax, apy = py - ay, apz = pz - az;
    float d1 = abx * apx + aby * apy + abz * apz;
    float d2 = acx * apx + acy * apy + acz * apz;
    float bpx = px - bx, bpy = py - by, bpz = pz - bz;
    float d3 = abx * bpx + aby * bpy + abz * bpz;
    float d4 = acx * bpx + acy * bpy + acz * bpz;
    float cpx = px - cx, cpy = py - cy, cpz = pz - cz;
    float d5 = abx * cpx + aby * cpy + abz * cpz;
    float d6 = acx * cpx + acy * cpy + acz * cpz;
    float vc = d1 * d4 - d3 * d2;
    float vb = d5 * d2 - d1 * d6;
    float va = d3 * d6 - d5 * d4;

    float inv = safe_div(1.0f, va + vb + vc);
    v = vb * inv;
    w = vc * inv;

    if (va <= 0.0f && d4 >= d3 && d5 >= d6) {
        float num = d4 - d3;
        float wbc = safe_div(num, num + (d5 - d6));
        v = 1.0f - wbc; w = wbc;
    }
    if (vb <= 0.0f && d2 >= 0.0f && d6 <= 0.0f) {
        v = 0.0f; w = safe_div(d2, d2 - d6);
    }
    if (d6 >= 0.0f && d5 <= d6) { v = 0.0f; w = 1.0f; }
    if (vc <= 0.0f && d1 >= 0.0f && d3 <= 0.0f) {
        v = safe_div(d1, d1 - d3); w = 0.0f;
    }
    if (d3 >= 0.0f && d4 <= d3) { v = 1.0f; w = 0.0f; }
    if (d1 <= 0.0f && d2 <= 0.0f) { v = 0.0f; w = 0.0f; }

    u = 1.0f - v - w;
}

// ---------------------------------------------------------------------------
// Per-pair test macro (2 points packed in f32x2). Uses triangle record values
// L0..L10 from the enclosing scope. 2D-frame formulation (see R9 comments):
// d^2 = h^2 + (inside ? 0 : min of three 2D segment distances).
// ---------------------------------------------------------------------------
#define TEST_PAIR(PX, PY, PZ, BEST0, BIDX0, BEST1, BIDX1)                     \
{                                                                             \
    u64 apx = ADD2(PX, L0.x), apy = ADD2(PY, L0.y), apz = ADD2(PZ, L1.x);     \
    u64 x = FMA2(L1.y, apx, FMA2(L2.x, apy, MUL2(L2.y, apz)));                \
    u64 y = FMA2(L3.x, apx, FMA2(L3.y, apy, MUL2(L4.x, apz)));                \
    u64 h = FMA2(L4.y, apx, FMA2(L5.x, apy, MUL2(L5.y, apz)));                \
    u64 xb = ADD2(x, L6.x);                                                   \
    float x0_, x1_, xb0_, xb1_;                                               \
    UPK(x, x0_, x1_); UPK(xb, xb0_, xb1_);                                    \
    u64 dxab = PK(fmaxf(xb0_, fminf(x0_, 0.0f)),                              \
                  fmaxf(xb1_, fminf(x1_, 0.0f)));                             \
    u64 dAB = FMA2(dxab, dxab, MUL2(y, y));                                   \
    u64 tca = CLAMP01_2(FMA2(x, L6.y, MUL2(y, L7.x)));                        \
    u64 dxc = FMA2(tca, L7.y, x);                                             \
    u64 dyc = FMA2(tca, L8.x, y);                                             \
    u64 dCA = FMA2(dxc, dxc, MUL2(dyc, dyc));                                 \
    u64 tbc = CLAMP01_2(FMA2(xb, L8.y, MUL2(y, L9.x)));                       \
    u64 dxb = FMA2(tbc, L9.y, xb);                                            \
    u64 dyb = FMA2(tbc, L8.x, y);                                             \
    u64 dBC = FMA2(dxb, dxb, MUL2(dyb, dyb));                                 \
    u64 s1 = FMA2(L10.y, x, MUL2(L7.y, y));                                   \
    u64 s2 = FMA2(L10.x, y, MUL2(L8.x, xb));                                  \
    float yy0_, yy1_, s10_, s11_, s20_, s21_;                                 \
    float dA0_, dA1_, dC0_, dC1_, dB0_, dB1_;                                 \
    UPK(y, yy0_, yy1_); UPK(s1, s10_, s11_); UPK(s2, s20_, s21_);             \
    UPK(dAB, dA0_, dA1_); UPK(dCA, dC0_, dC1_); UPK(dBC, dB0_, dB1_);         \
    float mn0_ = fminf(yy0_, fminf(s10_, s20_));                              \
    float mn1_ = fminf(yy1_, fminf(s11_, s21_));                              \
    float m0_ = (mn0_ >= 0.0f) ? 0.0f : fminf(fminf(dA0_, dC0_), dB0_);       \
    float m1_ = (mn1_ >= 0.0f) ? 0.0f : fminf(fminf(dA1_, dC1_), dB1_);       \
    u64 dist = FMA2(h, h, PK(m0_, m1_));                                      \
    float e0_, e1_; UPK(dist, e0_, e1_);                                      \
    if (e0_ < BEST0) { BEST0 = e0_; BIDX0 = fid; }                            \
    if (e1_ < BEST1) { BEST1 = e1_; BIDX1 = fid; }                            \
}

// ---------------------------------------------------------------------------
// Kernel 1: brute-force argmin search, 2D-frame, f32x2-packed, 4 pts/thread.
// grid = (NPTS/(BLK*PPT), NSPLIT) = (16, 64); one smem tile per block.
// smem record (22 packed-doubled u64 = 11 ulonglong2, 176 B/tri):
//   r0 (-ax,-ay)  r1 (-az,e1x)  r2 (e1y,e1z)  r3 (e2x,e2y)  r4 (e2z,nx)
//   r5 (ny,nz)    r6 (-b1,cs1)  r7 (cs2,-c1)  r8 (-c2,bcs1) r9 (bcs2,-bcx)
//   r10 (bcx,c2)
// ---------------------------------------------------------------------------
__global__ void __launch_bounds__(BLK, 4)
p2m_search_kernel(const float* __restrict__ tri, const float* __restrict__ pts)
{
    __shared__ ulonglong2 sT[TILE][NREC];

    const int tid = threadIdx.x;
    const int p0  = blockIdx.x * (BLK * PPT) + tid;
    const int p1  = p0 + BLK;               // all four in same batch:
    const int p2  = p0 + 2 * BLK;           // 512-aligned group, Q = 4096
    const int p3  = p0 + 3 * BLK;
    const int b   = p0 >> 12;
    const float* tb = tri + (size_t)b * FF * 9;

    const u64 pxA = PK(pts[p0 * 3 + 0], pts[p1 * 3 + 0]);
    const u64 pyA = PK(pts[p0 * 3 + 1], pts[p1 * 3 + 1]);
    const u64 pzA = PK(pts[p0 * 3 + 2], pts[p1 * 3 + 2]);
    const u64 pxB = PK(pts[p2 * 3 + 0], pts[p3 * 3 + 0]);
    const u64 pyB = PK(pts[p2 * 3 + 1], pts[p3 * 3 + 1]);
    const u64 pzB = PK(pts[p2 * 3 + 2], pts[p3 * 3 + 2]);

    const int f0 = blockIdx.y * FSEG;

    {   // one triangle per thread: build 2D frame record
        const float* s = tb + (size_t)(f0 + tid) * 9;
        float ax = s[0], ay = s[1], az = s[2];
        float bx = s[3], by = s[4], bz = s[5];
        float cx = s[6], cy = s[7], cz = s[8];
        float abx = bx - ax, aby = by - ay, abz = bz - az;
        float acx = cx - ax, acy = cy - ay, acz = cz - az;
        float abab = fmaf(abx, abx, fmaf(aby, aby, abz * abz));
        float acac = fmaf(acx, acx, fmaf(acy, acy, acz * acz));
        float abac = fmaf(abx, acx, fmaf(aby, acy, abz * acz));

        float rs1 = rsqrtf((abab == 0.0f) ? 1.0f : abab);
        float e1x = abx * rs1, e1y = aby * rs1, e1z = abz * rs1;
        float b1  = abab * rs1;                 // |ab|
        float c1  = abac * rs1;                 // ac . e1
        float qx = fmaf(-c1, e1x, acx);         // perp part of ac
        float qy = fmaf(-c1, e1y, acy);
        float qz = fmaf(-c1, e1z, acz);
        float qq = fmaf(qx, qx, fmaf(qy, qy, qz * qz));
        float rs2 = rsqrtf((qq == 0.0f) ? 1.0f : qq);
        float e2x = qx * rs2, e2y = qy * rs2, e2z = qz * rs2;
        float c2  = qq * rs2;                   // >= 0
        float nx = fmaf(e1y, e2z, -e1z * e2y);
        float ny = fmaf(e1z, e2x, -e1x * e2z);
        float nz = fmaf(e1x, e2y, -e1y * e2x);

        float invcc = 1.0f / ((acac == 0.0f) ? 1.0f : acac);
        float cs1 = c1 * invcc, cs2 = c2 * invcc;
        float bcx = c1 - b1;                    // 2D bc = (bcx, c2)
        float bcbc = fmaf(bcx, bcx, c2 * c2);
        float invbc = 1.0f / ((bcbc == 0.0f) ? 1.0f : bcbc);
        float bcs1 = bcx * invbc, bcs2 = c2 * invbc;

        ulonglong2* r = sT[tid];
        r[0]  = make_ulonglong2(PK(-ax, -ax),   PK(-ay, -ay));
        r[1]  = make_ulonglong2(PK(-az, -az),   PK(e1x, e1x));
        r[2]  = make_ulonglong2(PK(e1y, e1y),   PK(e1z, e1z));
        r[3]  = make_ulonglong2(PK(e2x, e2x),   PK(e2y, e2y));
        r[4]  = make_ulonglong2(PK(e2z, e2z),   PK(nx, nx));
        r[5]  = make_ulonglong2(PK(ny, ny),     PK(nz, nz));
        r[6]  = make_ulonglong2(PK(-b1, -b1),   PK(cs1, cs1));
        r[7]  = make_ulonglong2(PK(cs2, cs2),   PK(-c1, -c1));
        r[8]  = make_ulonglong2(PK(-c2, -c2),   PK(bcs1, bcs1));
        r[9]  = make_ulonglong2(PK(bcs2, bcs2), PK(-bcx, -bcx));
        r[10] = make_ulonglong2(PK(bcx, bcx),   PK(c2, c2));
    }
    __syncthreads();

    float bestA0 = CUDART_INF_F, bestA1 = CUDART_INF_F;
    float bestB0 = CUDART_INF_F, bestB1 = CUDART_INF_F;
    int   bidxA0 = f0, bidxA1 = f0, bidxB0 = f0, bidxB1 = f0;

    #pragma unroll 2
    for (int j = 0; j < TILE; ++j) {
        const ulonglong2* r = sT[j];
        const ulonglong2 L0 = r[0], L1 = r[1], L2 = r[2], L3 = r[3];
        const ulonglong2 L4 = r[4], L5 = r[5], L6 = r[6], L7 = r[7];
        const ulonglong2 L8 = r[8], L9 = r[9], L10 = r[10];
        const int fid = f0 + j;

        TEST_PAIR(pxA, pyA, pzA, bestA0, bidxA0, bestA1, bidxA1);
        TEST_PAIR(pxB, pyB, pzB, bestB0, bidxB0, bestB1, bidxB1);
    }

    u64 kA0 = ((u64)__float_as_uint(bestA0) << 32) | (u64)(unsigned)bidxA0;
    u64 kA1 = ((u64)__float_as_uint(bestA1) << 32) | (u64)(unsigned)bidxA1;
    u64 kB0 = ((u64)__float_as_uint(bestB0) << 32) | (u64)(unsigned)bidxB0;
    u64 kB1 = ((u64)__float_as_uint(bestB1) << 32) | (u64)(unsigned)bidxB1;
    atomicMax(&g_key[p0], ~kA0);
    atomicMax(&g_key[p1], ~kA1);
    atomicMax(&g_key[p2], ~kB0);
    atomicMax(&g_key[p3], ~kB1);
}

// ---------------------------------------------------------------------------
// Kernel 2: read winning triangle (complemented key), reset slot for next
// graph replay, recompute exact reference bary, clamp, gather, write outputs.
// Output (float32): residual[8192*3] | normals[8192*3] | cmaps[8192*3] | idx[8192]
// ---------------------------------------------------------------------------
__global__ void p2m_finalize_kernel(
    const float* __restrict__ tri, const float* __restrict__ pts,
    const float* __restrict__ nrm, const float* __restrict__ cmp,
    const int*   __restrict__ faces, float* __restrict__ out)
{
    const int pid = blockIdx.x * blockDim.x + threadIdx.x;
    if (pid >= NPTS) return;

    const u64 raw = g_key[pid];
    g_key[pid] = 0ull;                         // reset for next replay
    const int bidx = (int)((~raw) & 0xFFFFFFFFull);

    const int b = pid >> 12;
    const size_t fbase = (size_t)(b * FF + bidx);

    const float px = pts[pid * 3 + 0];
    const float py = pts[pid * 3 + 1];
    const float pz = pts[pid * 3 + 2];

    const float* t = tri + fbase * 9;
    float ax = t[0], ay = t[1], az = t[2];
    float bx = t[3], by = t[4], bz = t[5];
    float cx = t[6], cy = t[7], cz = t[8];

    float u, v, w;
    bary_uvw_exact(ax, ay, az, bx, by, bz, cx, cy, cz, px, py, pz, u, v, w);

    u = fminf(fmaxf(u, 0.0f), 1.0f);
    v = fminf(fmaxf(v, 0.0f), 1.0f);
    w = fminf(fmaxf(w, 0.0f), 1.0f);

    out[pid * 3 + 0] = (u * ax + v * bx + w * cx) - px;
    out[pid * 3 + 1] = (u * ay + v * by + w * cy) - py;
    out[pid * 3 + 2] = (u * az + v * bz + w * cz) - pz;

    const float* n = nrm + fbase * 9;
    out[NPTS * 3 + pid * 3 + 0] = u * n[0] + v * n[3] + w * n[6];
    out[NPTS * 3 + pid * 3 + 1] = u * n[1] + v * n[4] + w * n[7];
    out[NPTS * 3 + pid * 3 + 2] = u * n[2] + v * n[5] + w * n[8];

    const float* cm = cmp + fbase * 9;
    out[NPTS * 6 + pid * 3 + 0] = u * cm[0] + v * cm[3] + w * cm[6];
    out[NPTS * 6 + pid * 3 + 1] = u * cm[1] + v * cm[4] + w * cm[7];
    out[NPTS * 6 + pid * 3 + 2] = u * cm[2] + v * cm[5] + w * cm[8];

    int k = (u >= v && u >= w) ? 0 : ((v >= w) ? 1 : 2);
    out[NPTS * 9 + pid] = (float)faces[fbase * 3 + k];
}

extern "C" void kernel_launch(void* const* d_in, const int* in_sizes, int n_in,
                              void* d_out, int out_size)
{
    const float* tri   = (const float*)d_in[0];   // [B,F,3,3]
    const float* pts   = (const float*)d_in[1];   // [B,Q,3]
    const float* nrm   = (const float*)d_in[2];   // [B,F,3,3]
    const float* cmp   = (const float*)d_in[3];   // [B,F,3,3]
    const int*   faces = (const int*)  d_in[4];   // [B,F,3]
    float* out = (float*)d_out;

    dim3 grid1(NPTS / (BLK * PPT), NSPLIT);       // (16, 64)
    p2m_search_kernel<<<grid1, BLK>>>(tri, pts);
    p2m_finalize_kernel<<<NPTS / 256, 256>>>(tri, pts, nrm, cmp, faces, out);
}